// round 7
// baseline (speedup 1.0000x reference)
#include <cuda_runtime.h>

// Problem constants (fixed by the dataset: pcd [8, 4096, 3] fp32, k = 5)
#define NB 8
#define NPTS 4096
#define KNN 5
#define NSPLIT 4
#define MSEG (NPTS / NSPLIT)       // 1024 points per segment
#define TPB 128
#define CHUNKS (NPTS / TPB)        // 32 query chunks per batch
#define BUFCAP 17                  // per-thread smem candidate slots
#define FLUSH_AT 9                 // flush when any lane has >= 9 (next 8 can't overflow)

// Scratch (allocation-free rule -> __device__ globals)
__device__ float g_key[NSPLIT][NB * NPTS * KNN];
__device__ int   g_idx[NSPLIT][NB * NPTS * KNN];
__device__ float g_partial[NB * 16];   // per-merge-CTA trace partial sums

// --------------------------------------------------------------------------
// Kernel A: per-(query, point-segment) top-5 scan, deferred insertion via a
// PREDICATED shared-memory candidate buffer (no branch in the hot loop, so
// warp-coherent insert events cost nothing extra).
// CTA = 128 queries x one quarter of the points (1024 pts in 16KB smem as
// float4(x,y,z,|p|^2)); 17-slot per-thread buffer interleaved in 17KB smem.
// key_j = |p_j|^2 - 2 q.p_j (monotone in d^2; strict '<' in the exact insert
// keeps the lowest index on ties, matching jax.lax.top_k).
// --------------------------------------------------------------------------
__global__ __launch_bounds__(TPB) void knn_scan_kernel(const float* __restrict__ pcd)
{
    __shared__ float4 sh[MSEG];                 // 16 KB
    __shared__ float2 sbuf[BUFCAP * TPB];       // 17 KB, slot i of thread t at [i*TPB+t]

    const int seg   = blockIdx.x & (NSPLIT - 1);
    const int chunk = (blockIdx.x >> 2) % CHUNKS;
    const int b     = blockIdx.x / (NSPLIT * CHUNKS);

    const float* base = pcd + (size_t)b * NPTS * 3;
    const int p0 = seg * MSEG;

    for (int p = threadIdx.x; p < MSEG; p += TPB) {
        float x = base[(p0 + p) * 3 + 0];
        float y = base[(p0 + p) * 3 + 1];
        float z = base[(p0 + p) * 3 + 2];
        sh[p] = make_float4(x, y, z, fmaf(x, x, fmaf(y, y, z * z)));
    }
    __syncthreads();

    const int qi = chunk * TPB + threadIdx.x;
    const float qx = base[qi * 3 + 0];
    const float qy = base[qi * 3 + 1];
    const float qz = base[qi * 3 + 2];
    const float nx = -2.0f * qx, ny = -2.0f * qy, nz = -2.0f * qz;

    // Exact sorted top-5 (ascending); named scalars -> registers.
    float bk0 = 3.4e38f, bk1 = 3.4e38f, bk2 = 3.4e38f, bk3 = 3.4e38f, bk4 = 3.4e38f;
    int   bi0 = 0, bi1 = 0, bi2 = 0, bi3 = 0, bi4 = 0;

#define INSERT(KEY, JIDX)                                                     \
    {                                                                         \
        float key = (KEY);                                                    \
        if (key < bk4) {                                                      \
            bool lt0 = key < bk0;                                             \
            bool lt1 = key < bk1;                                             \
            bool lt2 = key < bk2;                                             \
            bool lt3 = key < bk3;                                             \
            bk4 = lt3 ? bk3 : key;  bi4 = lt3 ? bi3 : (JIDX);                 \
            if (lt3) { bk3 = lt2 ? bk2 : key;  bi3 = lt2 ? bi2 : (JIDX); }    \
            if (lt2) { bk2 = lt1 ? bk1 : key;  bi2 = lt1 ? bi1 : (JIDX); }    \
            if (lt1) { bk1 = lt0 ? bk0 : key;  bi1 = lt0 ? bi0 : (JIDX); }    \
            if (lt0) { bk0 = key;              bi0 = (JIDX); }                \
        }                                                                     \
    }

    float2* mybuf = sbuf + threadIdx.x;   // stride TPB between slots
    int cnt = 0;
    float thr = 3.4e38f;                  // stale >= true 5th key: never drops

    for (int j = 0; j < MSEG; j += 8) {
#pragma unroll
        for (int u = 0; u < 8; u++) {
            float4 p = sh[j + u];
            float key = fmaf(p.x, nx, fmaf(p.y, ny, fmaf(p.z, nz, p.w)));
            // Predicated append: FSETP + @P IMAD/STS.64/IADD, no branch.
            if (key < thr) {
                mybuf[cnt * TPB] = make_float2(key, __int_as_float(p0 + j + u));
                cnt++;
            }
        }
        if (__any_sync(0xffffffffu, cnt >= FLUSH_AT)) {
            for (int i = 0; i < cnt; i++) {
                float2 e = mybuf[i * TPB];
                INSERT(e.x, __float_as_int(e.y));
            }
            cnt = 0;
            thr = bk4;
        }
    }
    for (int i = 0; i < cnt; i++) {
        float2 e = mybuf[i * TPB];
        INSERT(e.x, __float_as_int(e.y));
    }
#undef INSERT

    const size_t o = ((size_t)b * NPTS + qi) * KNN;
    g_key[seg][o + 0] = bk0;  g_idx[seg][o + 0] = bi0;
    g_key[seg][o + 1] = bk1;  g_idx[seg][o + 1] = bi1;
    g_key[seg][o + 2] = bk2;  g_idx[seg][o + 2] = bi2;
    g_key[seg][o + 3] = bk3;  g_idx[seg][o + 3] = bi3;
    g_key[seg][o + 4] = bk4;  g_idx[seg][o + 4] = bi4;
}

// --------------------------------------------------------------------------
// Kernel B: merge the four sorted 5-lists per query by rank counting.
// Global order = (key, segment, in-list position): earlier segment wins ties
// ('<=' vs '<'). Gather neighbors, compute covariance trace with the
// reference's centroid-then-centered numerics. Emits per-CTA partial sums.
// --------------------------------------------------------------------------
__global__ __launch_bounds__(256) void merge_trace_kernel(
    const float* __restrict__ pcd, float* __restrict__ out)
{
    __shared__ float warp_sums[8];

    const int t = blockIdx.x * 256 + threadIdx.x;   // 0 .. NB*NPTS-1
    const int b = t >> 12;

    float k[NSPLIT][KNN];
    int   ix[NSPLIT][KNN];
    const size_t o = (size_t)t * KNN;
#pragma unroll
    for (int s = 0; s < NSPLIT; s++)
#pragma unroll
        for (int i = 0; i < KNN; i++) {
            k[s][i]  = g_key[s][o + i];
            ix[s][i] = g_idx[s][o + i];
        }

    float w[NSPLIT][KNN];
#pragma unroll
    for (int s = 0; s < NSPLIT; s++) {
#pragma unroll
        for (int i = 0; i < KNN; i++) {
            int r = i;
#pragma unroll
            for (int u = 0; u < NSPLIT; u++) {
                if (u == s) continue;
#pragma unroll
                for (int j = 0; j < KNN; j++) {
                    if (u < s) r += (k[u][j] <= k[s][i]);
                    else       r += (k[u][j] <  k[s][i]);
                }
            }
            w[s][i] = (r < KNN) ? 1.0f : 0.0f;
        }
    }

    const float* base = pcd + (size_t)b * NPTS * 3;
    float px[NSPLIT][KNN], py[NSPLIT][KNN], pz[NSPLIT][KNN];
#pragma unroll
    for (int s = 0; s < NSPLIT; s++)
#pragma unroll
        for (int i = 0; i < KNN; i++) {
            int idx = ix[s][i];
            px[s][i] = base[idx * 3 + 0];
            py[s][i] = base[idx * 3 + 1];
            pz[s][i] = base[idx * 3 + 2];
        }

    float sx = 0.f, sy = 0.f, sz = 0.f;
#pragma unroll
    for (int s = 0; s < NSPLIT; s++)
#pragma unroll
        for (int i = 0; i < KNN; i++) {
            sx = fmaf(w[s][i], px[s][i], sx);
            sy = fmaf(w[s][i], py[s][i], sy);
            sz = fmaf(w[s][i], pz[s][i], sz);
        }
    const float inv_k = 1.0f / (float)KNN;
    const float mx = sx * inv_k, my = sy * inv_k, mz = sz * inv_k;

    float tr = 0.f;
#pragma unroll
    for (int s = 0; s < NSPLIT; s++)
#pragma unroll
        for (int i = 0; i < KNN; i++) {
            float dx = px[s][i] - mx, dy = py[s][i] - my, dz = pz[s][i] - mz;
            tr = fmaf(w[s][i], fmaf(dx, dx, fmaf(dy, dy, dz * dz)), tr);
        }
    tr *= 1.0f / (float)(KNN - 1);
    out[t] = tr;

    float s0 = tr;
#pragma unroll
    for (int off = 16; off > 0; off >>= 1)
        s0 += __shfl_down_sync(0xffffffffu, s0, off);
    if ((threadIdx.x & 31) == 0) warp_sums[threadIdx.x >> 5] = s0;
    __syncthreads();
    if (threadIdx.x < 32) {
        float v = (threadIdx.x < 8) ? warp_sums[threadIdx.x] : 0.0f;
#pragma unroll
        for (int off = 4; off > 0; off >>= 1)
            v += __shfl_down_sync(0xffffffffu, v, off);
        if (threadIdx.x == 0) g_partial[blockIdx.x] = v;
    }
}

// --------------------------------------------------------------------------
// Kernel C: normalize. 4 CTAs per batch; each redundantly sums its batch's
// 16 partials with a fixed-order tree (deterministic) and scales its quarter.
// --------------------------------------------------------------------------
__global__ __launch_bounds__(256) void finalize_kernel(float* __restrict__ out)
{
    __shared__ float s_inv;
    const int b = blockIdx.x >> 2;
    const int quarter = blockIdx.x & 3;

    if (threadIdx.x < 32) {
        float v = (threadIdx.x < 16) ? g_partial[b * 16 + threadIdx.x] : 0.0f;
#pragma unroll
        for (int off = 8; off > 0; off >>= 1)
            v += __shfl_down_sync(0xffffffffu, v, off);
        if (threadIdx.x == 0) s_inv = 1.0f / (v + 1e-8f);
    }
    __syncthreads();

    const float inv = s_inv;
    float* o = out + (size_t)b * NPTS + quarter * (NPTS / 4);
#pragma unroll
    for (int i = 0; i < (NPTS / 4) / 256; i++)
        o[i * 256 + threadIdx.x] *= inv;
}

extern "C" void kernel_launch(void* const* d_in, const int* in_sizes, int n_in,
                              void* d_out, int out_size)
{
    const float* pcd = (const float*)d_in[0];
    float* out = (float*)d_out;

    knn_scan_kernel<<<NB * CHUNKS * NSPLIT, TPB>>>(pcd);      // 1024 CTAs
    merge_trace_kernel<<<(NB * NPTS) / 256, 256>>>(pcd, out); // 128 CTAs
    finalize_kernel<<<NB * 4, 256>>>(out);                    // 32 CTAs
}